// round 12
// baseline (speedup 1.0000x reference)
#include <cuda_runtime.h>
#include <cuda_bf16.h>
#include <cstdint>

#define NB 256

// Scratch: [b][mod][proj(Q,K,V)][640][100] fp32
__device__ float g_scr[196608000UL];
__device__ __nv_bfloat16 g_w_hi[6144000];
__device__ __nv_bfloat16 g_w_lo[6144000];
__device__ __nv_bfloat16 g_xt_hi[81920000UL];   // [b][l=100][c=3200]
__device__ __nv_bfloat16 g_xt_lo[81920000UL];

struct Params {
    const float* w[24];  // [mod][wq,wk,wv,bq,bk,bv]
};

// ---------------------------------------------------------------- helpers
__device__ __forceinline__ uint32_t smem_to_u32(const void* p) {
    uint32_t a;
    asm("{ .reg .u64 t; cvta.to.shared.u64 t, %1; cvt.u32.u64 %0, t; }" : "=r"(a) : "l"(p));
    return a;
}
__device__ __forceinline__ void ldsm4(uint32_t* r, uint32_t addr) {
    asm volatile("ldmatrix.sync.aligned.m8n8.x4.shared.b16 {%0,%1,%2,%3}, [%4];"
        : "=r"(r[0]), "=r"(r[1]), "=r"(r[2]), "=r"(r[3]) : "r"(addr));
}
__device__ __forceinline__ void ldsm2(uint32_t* r, uint32_t addr) {
    asm volatile("ldmatrix.sync.aligned.m8n8.x2.shared.b16 {%0,%1}, [%2];"
        : "=r"(r[0]), "=r"(r[1]) : "r"(addr));
}
__device__ __forceinline__ void mma16816(float* c, const uint32_t* a, uint32_t b0, uint32_t b1) {
    asm volatile("mma.sync.aligned.m16n8k16.row.col.f32.bf16.bf16.f32 "
        "{%0,%1,%2,%3}, {%4,%5,%6,%7}, {%8,%9}, {%0,%1,%2,%3};"
        : "+f"(c[0]), "+f"(c[1]), "+f"(c[2]), "+f"(c[3])
        : "r"(a[0]), "r"(a[1]), "r"(a[2]), "r"(a[3]), "r"(b0), "r"(b1));
}
__device__ __forceinline__ unsigned long long pack2(float x, float y) {
    unsigned long long r;
    asm("mov.b64 %0, {%1, %2};" : "=l"(r) : "f"(x), "f"(y));
    return r;
}
__device__ __forceinline__ void unpack2(unsigned long long v, float& x, float& y) {
    asm("mov.b64 {%0, %1}, %2;" : "=f"(x), "=f"(y) : "l"(v));
}
__device__ __forceinline__ void ffma2(unsigned long long& c, unsigned long long a, unsigned long long b) {
    asm("fma.rn.f32x2 %0, %1, %2, %0;" : "+l"(c) : "l"(a), "l"(b));
}
__device__ __forceinline__ unsigned long long lds_u64(uint32_t a) {
    unsigned long long v;
    asm volatile("ld.shared.b64 %0, [%1];" : "=l"(v) : "r"(a));
    return v;
}

// ============================================================================
// prep_w: fp32 weights -> bf16 hi/lo
// ============================================================================
__global__ void prep_w(Params p) {
    const int seg = blockIdx.y;
    const int mod = seg / 3;
    const int Cin = (mod == 1) ? 1280 : 640;
    const size_t offs[12] = {0, 409600, 819200, 1228800, 2048000, 2867200,
                             3686400, 4096000, 4505600, 4915200, 5324800, 5734400};
    const float* __restrict__ w = p.w[mod * 6 + (seg % 3)];
    const size_t off = offs[seg];
    const size_t n = (size_t)640 * Cin;
    for (size_t i = (size_t)blockIdx.x * blockDim.x + threadIdx.x; i < n; i += (size_t)gridDim.x * blockDim.x) {
        float v = w[i];
        __nv_bfloat16 h = __float2bfloat16(v);
        g_w_hi[off + i] = h;
        g_w_lo[off + i] = __float2bfloat16(v - __bfloat162float(h));
    }
}

// ============================================================================
// prep_x: x[b][C=3200][L=100] fp32 -> XT[b][l][c] bf16 hi/lo
// ============================================================================
__global__ void prep_x(const float* __restrict__ x) {
    __shared__ float t[32][33];
    const int b = blockIdx.z, ct = blockIdx.x, lt = blockIdx.y;
    const int tx = threadIdx.x, ty = threadIdx.y;
    const float* xb = x + (size_t)b * 320000;
    const int l = lt * 32 + tx;
    #pragma unroll
    for (int j = 0; j < 4; j++) {
        int c = ct * 32 + ty + j * 8;
        t[ty + j * 8][tx] = (l < 100) ? xb[(size_t)c * 100 + l] : 0.0f;
    }
    __syncthreads();
    const int c_out = ct * 32 + tx;
    const size_t xtb = (size_t)b * 320000;
    #pragma unroll
    for (int j = 0; j < 4; j++) {
        int lo_ = lt * 32 + ty + j * 8;
        if (lo_ < 100) {
            float v = t[tx][ty + j * 8];
            __nv_bfloat16 h = __float2bfloat16(v);
            size_t o = xtb + (size_t)lo_ * 3200 + c_out;
            g_xt_hi[o] = h;
            g_xt_lo[o] = __float2bfloat16(v - __bfloat162float(h));
        }
    }
}

// ============================================================================
// qkv_mma: R9 MMA body + 3-stage cp.async pipeline, ONE __syncthreads/chunk.
// Stage being filled at iter c is (c+2)%3 — last read at iter c-1, protected
// by the top-of-loop barrier.  smem = 3*37120 = 111360 B (2 CTAs/SM).
// ============================================================================
#define STAGE  37120u
#define OFF_AH 0u
#define OFF_AL 10240u
#define OFF_BH 20480u
#define OFF_BL 28800u

__global__ __launch_bounds__(256, 2) void qkv_mma(Params p) {
    extern __shared__ __align__(16) char smem_raw[];
    const uint32_t sb = smem_to_u32(smem_raw);

    const int tid = threadIdx.x;
    int bid = blockIdx.x;
    const int mtile = bid % 5; bid /= 5;
    const int proj  = bid % 3; bid /= 3;
    const int mod   = bid & 3;
    const int b     = bid >> 2;

    const int Cin = (mod == 1) ? 1280 : 640;
    const int nch = Cin >> 5;
    const int mbase = mtile * 128;

    const size_t offs[12] = {0, 409600, 819200, 1228800, 2048000, 2867200,
                             3686400, 4096000, 4505600, 4915200, 5324800, 5734400};
    const int c0m_tab[4] = {2560, 640, 1920, 0};
    const size_t woff = offs[mod * 3 + proj];
    const size_t xoff = (size_t)b * 320000 + c0m_tab[mod];
    const float* __restrict__ bias = p.w[mod * 6 + 3 + proj];
    float* __restrict__ O = g_scr + ((((size_t)b * 4 + mod) * 3 + proj) * 640 + mbase) * 100;

    const __nv_bfloat16* __restrict__ Wh = g_w_hi + woff;
    const __nv_bfloat16* __restrict__ Wl = g_w_lo + woff;
    const __nv_bfloat16* __restrict__ Xh = g_xt_hi + xoff;
    const __nv_bfloat16* __restrict__ Xl = g_xt_lo + xoff;

    // zero B pad rows 100..103 (3 stages, hi+lo)
    for (int idx = tid; idx < 480; idx += 256) {
        int st = idx / 160, rest = idx % 160;
        int buf = rest / 80, r2 = rest % 80;
        uint32_t a = sb + (uint32_t)st * STAGE + (buf ? OFF_BL : OFF_BH)
                   + (uint32_t)(100 + r2 / 20) * 80 + (uint32_t)(r2 % 20) * 4;
        asm volatile("st.shared.b32 [%0], %1;" :: "r"(a), "r"(0) : "memory");
    }

    auto issue_chunk = [&](int st, int c) {
        const int k0 = c << 5;
        const uint32_t stg = sb + (uint32_t)st * STAGE;
        for (int idx = tid; idx < 1824; idx += 256) {
            const __nv_bfloat16* src;
            uint32_t dst;
            if (idx < 1024) {
                int buf = idx >> 9, r = (idx >> 2) & 127, seg = idx & 3;
                src = (buf ? Wl : Wh) + (size_t)(mbase + r) * Cin + k0 + seg * 8;
                dst = stg + (buf ? OFF_AL : OFF_AH) + (uint32_t)r * 80 + (uint32_t)seg * 16;
            } else {
                int j = idx - 1024;
                int n = j >> 3, rem = j & 7;
                int buf = rem >> 2, seg = rem & 3;
                src = (buf ? Xl : Xh) + (size_t)n * 3200 + k0 + seg * 8;
                dst = stg + (buf ? OFF_BL : OFF_BH) + (uint32_t)n * 80 + (uint32_t)seg * 16;
            }
            asm volatile("cp.async.cg.shared.global [%0], [%1], 16;" :: "r"(dst), "l"(src) : "memory");
        }
        asm volatile("cp.async.commit_group;" ::: "memory");
    };

    const int w = tid >> 5, lane = tid & 31;
    const int rloc = w * 16 + (lane >> 2);
    const int qd = lane & 3;

    const uint32_t aoff = (uint32_t)(w * 16 + (lane & 15)) * 80 + (uint32_t)(lane >> 4) * 16;
    const uint32_t b4off = (uint32_t)(((lane >> 4) * 8) + (lane & 7)) * 80 + (uint32_t)((lane >> 3) & 1) * 16;
    const uint32_t b2off = (uint32_t)(lane & 7) * 80 + (uint32_t)((lane >> 3) & 1) * 16;

    float acc[13][4];
    #pragma unroll
    for (int t = 0; t < 13; t++)
        #pragma unroll
        for (int i = 0; i < 4; i++) acc[t][i] = 0.0f;

    issue_chunk(0, 0);
    issue_chunk(1, 1);

    int stage = 0;
    for (int c = 0; c < nch; c++) {
        __syncthreads();   // all warps done reading stage (c+2)%3 (MMA'd at c-1)
        if (c + 2 < nch) {
            int st2 = stage + 2; if (st2 >= 3) st2 -= 3;
            issue_chunk(st2, c + 2);
            asm volatile("cp.async.wait_group 2;" ::: "memory");
        } else if (c + 1 < nch) {
            asm volatile("cp.async.wait_group 1;" ::: "memory");
        } else {
            asm volatile("cp.async.wait_group 0;" ::: "memory");
        }
        __syncthreads();   // chunk c visible to all warps

        const uint32_t stg = sb + (uint32_t)stage * STAGE;
        const uint32_t aAh = stg + OFF_AH + aoff;
        const uint32_t aAl = stg + OFF_AL + aoff;
        const uint32_t aBh4 = stg + OFF_BH + b4off;
        const uint32_t aBl4 = stg + OFF_BL + b4off;
        const uint32_t aBh2 = stg + OFF_BH + 7680u + b2off;
        const uint32_t aBl2 = stg + OFF_BL + 7680u + b2off;

        #pragma unroll
        for (int s16 = 0; s16 < 2; s16++) {
            const uint32_t ko = (uint32_t)s16 * 32;
            uint32_t ah[4], al[4];
            ldsm4(ah, aAh + ko);
            ldsm4(al, aAl + ko);
            #pragma unroll
            for (int pr = 0; pr < 6; pr++) {
                uint32_t bh[4], bl[4];
                ldsm4(bh, aBh4 + (uint32_t)pr * 1280 + ko);
                ldsm4(bl, aBl4 + (uint32_t)pr * 1280 + ko);
                mma16816(acc[2 * pr],     ah, bh[0], bh[1]);
                mma16816(acc[2 * pr + 1], ah, bh[2], bh[3]);
                mma16816(acc[2 * pr],     ah, bl[0], bl[1]);
                mma16816(acc[2 * pr + 1], ah, bl[2], bl[3]);
                mma16816(acc[2 * pr],     al, bh[0], bh[1]);
                mma16816(acc[2 * pr + 1], al, bh[2], bh[3]);
            }
            {
                uint32_t bh[2], bl[2];
                ldsm2(bh, aBh2 + ko);
                ldsm2(bl, aBl2 + ko);
                mma16816(acc[12], ah, bh[0], bh[1]);
                mma16816(acc[12], ah, bl[0], bl[1]);
                mma16816(acc[12], al, bh[0], bh[1]);
            }
        }
        if (++stage == 3) stage = 0;
    }

    const float bv0 = bias[mbase + rloc];
    const float bv1 = bias[mbase + rloc + 8];
    float* o0 = O + (size_t)rloc * 100;
    float* o1 = o0 + 800;
    #pragma unroll
    for (int t = 0; t < 13; t++) {
        int col = t * 8 + qd * 2;
        if (col < 100) {
            float2 v0 = make_float2(acc[t][0] + bv0, acc[t][1] + bv0);
            float2 v1 = make_float2(acc[t][2] + bv1, acc[t][3] + bv1);
            *(float2*)(o0 + col) = v0;
            *(float2*)(o1 + col) = v1;
        }
    }
}

// ============================================================================
// Pass 2: attention v4 — EXACT R9 body (best measured: 804us).
// ============================================================================
#define PT_OFF   0
#define U_OFF    10000
#define KC_OFF   3328
#define PART_OFF 16656
#define ROW_OFF  17656
#define ATTN_SMEM 71040

__global__ __launch_bounds__(256, 3) void attn_kernel(float* __restrict__ out) {
    extern __shared__ __align__(16) float sm[];
    const int tid = threadIdx.x;
    const int bm = blockIdx.x;
    const int mod = bm & 3, b = bm >> 2;

    const float* __restrict__ Q = g_scr + (size_t)bm * 192000;
    const float* __restrict__ K = Q + 64000;
    const float* __restrict__ V = Q + 128000;
    float* __restrict__ O = out + ((size_t)mod * NB + b) * 64000;

    float* Pt   = sm + PT_OFF;
    float* U    = sm + U_OFF;
    float* part = sm + PART_OFF;
    float* row  = sm + ROW_OFF;
    const uint32_t u_b = smem_to_u32(U);
    const uint32_t pt_b = smem_to_u32(Pt);

    const bool act = tid < 250;
    const int lg = tid % 25;
    const int mg = tid / 25;
    const int m0 = mg * 10;

    unsigned long long acc[4][5];
    #pragma unroll
    for (int t = 0; t < 4; t++)
        #pragma unroll
        for (int j = 0; j < 5; j++) acc[t][j] = 0ULL;

    for (int c0 = 0; c0 < 640; c0 += 32) {
        for (int idx = tid; idx < 1600; idx += 256) {
            int which = idx >= 800;
            int i2 = idx - which * 800;
            int rw = i2 / 25, c4 = (i2 % 25) * 4;
            const float* src = (which ? K : Q) + (size_t)(c0 + rw) * 100 + c4;
            *(float4*)(U + which * KC_OFF + rw * 104 + c4) = *(const float4*)src;
        }
        __syncthreads();
        if (act) {
            #pragma unroll 2
            for (int kk = 0; kk < 32; kk++) {
                const float* qrow = U + kk * 104;
                unsigned long long qd_[4];
                #pragma unroll
                for (int t = 0; t < 4; t++) {
                    float qv = qrow[lg + 25 * t];
                    qd_[t] = pack2(qv, qv);
                }
                const uint32_t kb = u_b + (uint32_t)(KC_OFF + kk * 104 + m0) * 4;
                #pragma unroll
                for (int j = 0; j < 5; j++) {
                    unsigned long long kv = lds_u64(kb + (uint32_t)j * 8);
                    ffma2(acc[0][j], qd_[0], kv);
                    ffma2(acc[1][j], qd_[1], kv);
                    ffma2(acc[2][j], qd_[2], kv);
                    ffma2(acc[3][j], qd_[3], kv);
                }
            }
        }
        __syncthreads();
    }

    if (act) {
        #pragma unroll
        for (int t = 0; t < 4; t++) {
            float mx = -3.4e38f;
            #pragma unroll
            for (int j = 0; j < 5; j++) {
                float lo, hi;
                unpack2(acc[t][j], lo, hi);
                mx = fmaxf(mx, fmaxf(lo, hi));
            }
            part[(lg + 25 * t) * 10 + mg] = mx;
        }
    }
    __syncthreads();
    if (tid < 100) {
        float m = -3.4e38f;
        #pragma unroll
        for (int g = 0; g < 10; g++) m = fmaxf(m, part[tid * 10 + g]);
        row[tid] = m;
    }
    __syncthreads();
    if (act) {
        #pragma unroll
        for (int t = 0; t < 4; t++) {
            float mr = row[lg + 25 * t];
            float s = 0.0f;
            #pragma unroll
            for (int j = 0; j < 5; j++) {
                float lo, hi;
                unpack2(acc[t][j], lo, hi);
                float e0 = __expf(lo - mr), e1 = __expf(hi - mr);
                s += e0 + e1;
                acc[t][j] = pack2(e0, e1);
            }
            part[(lg + 25 * t) * 10 + mg] = s;
        }
    }
    __syncthreads();
    if (tid < 100) {
        float s = 0.0f;
        #pragma unroll
        for (int g = 0; g < 10; g++) s += part[tid * 10 + g];
        row[tid] = 1.0f / s;
    }
    __syncthreads();
    if (act) {
        #pragma unroll
        for (int t = 0; t < 4; t++) {
            int l = lg + 25 * t;
            float inv = row[l];
            #pragma unroll
            for (int j = 0; j < 5; j++) {
                float lo, hi;
                unpack2(acc[t][j], lo, hi);
                int m = m0 + 2 * j;
                Pt[m * 100 + l]       = lo * inv;
                Pt[(m + 1) * 100 + l] = hi * inv;
            }
        }
    }

    const int cgC = tid % 16, igC = tid / 16;
    const bool actC = igC < 10;
    const int i0 = igC * 10;

    for (int chunk = 0; chunk < 10; chunk++) {
        __syncthreads();
        for (int idx = tid; idx < 1600; idx += 256) {
            int rw = idx / 25, c4 = (idx % 25) * 4;
            *(float4*)(U + rw * 100 + c4) =
                *(const float4*)(V + (size_t)(chunk * 64 + rw) * 100 + c4);
        }
        __syncthreads();
        if (actC) {
            unsigned long long pacc[4][5];
            #pragma unroll
            for (int u = 0; u < 4; u++)
                #pragma unroll
                for (int s = 0; s < 5; s++) pacc[u][s] = 0ULL;
            const uint32_t pb = pt_b + (uint32_t)i0 * 4;
            #pragma unroll 4
            for (int j = 0; j < 100; j++) {
                unsigned long long vd[4];
                #pragma unroll
                for (int u = 0; u < 4; u++) {
                    float vv = U[(cgC + 16 * u) * 100 + j];
                    vd[u] = pack2(vv, vv);
                }
                const uint32_t pj = pb + (uint32_t)j * 400;
                #pragma unroll
                for (int s = 0; s < 5; s++) {
                    unsigned long long pp = lds_u64(pj + (uint32_t)s * 8);
                    ffma2(pacc[0][s], vd[0], pp);
                    ffma2(pacc[1][s], vd[1], pp);
                    ffma2(pacc[2][s], vd[2], pp);
                    ffma2(pacc[3][s], vd[3], pp);
                }
            }
            #pragma unroll
            for (int u = 0; u < 4; u++) {
                int c_ = chunk * 64 + cgC + 16 * u;
                float* orow = O + (size_t)c_ * 100 + i0;
                #pragma unroll
                for (int s = 0; s < 5; s++) {
                    float a0, a1;
                    unpack2(pacc[u][s], a0, a1);
                    *(float2*)(orow + 2 * s) = make_float2(a0, a1);
                }
            }
        }
    }
}

extern "C" void kernel_launch(void* const* d_in, const int* in_sizes, int n_in,
                              void* d_out, int out_size) {
    const float* x = (const float*)d_in[0];
    Params p;
    for (int i = 0; i < 24; i++) p.w[i] = (const float*)d_in[1 + i];

    prep_w<<<dim3(800, 12), 256>>>(p);
    prep_x<<<dim3(100, 4, 256), dim3(32, 8)>>>(x);

    cudaFuncSetAttribute(qkv_mma, cudaFuncAttributeMaxDynamicSharedMemorySize, 111360);
    qkv_mma<<<15360, 256, 111360>>>(p);

    cudaFuncSetAttribute(attn_kernel, cudaFuncAttributeMaxDynamicSharedMemorySize, ATTN_SMEM);
    attn_kernel<<<1024, 256, ATTN_SMEM>>>((float*)d_out);
}

// round 13
// speedup vs baseline: 1.2172x; 1.2172x over previous
#include <cuda_runtime.h>
#include <cuda_bf16.h>
#include <cstdint>

#define NB 256

// Scratch: [b][mod][slot(0,1,2)][640][100] fp32
// small mods: slot0 = T (= WqT*Wk*x), slot2 = V.  thigh: slot0=Q, slot1=K, slot2=V.
__device__ float g_scr[196608000UL];
__device__ __nv_bfloat16 g_w_hi[6144000];
__device__ __nv_bfloat16 g_w_lo[6144000];
__device__ __nv_bfloat16 g_xt_hi[81920000UL];   // [b][l=100][c=3200]
__device__ __nv_bfloat16 g_xt_lo[81920000UL];

struct Params {
    const float* w[24];  // [mod][wq,wk,wv,bq,bk,bv]
};

__constant__ size_t c_offs[12] = {0, 409600, 819200, 1228800, 2048000, 2867200,
                                  3686400, 4096000, 4505600, 4915200, 5324800, 5734400};

// ---------------------------------------------------------------- helpers
__device__ __forceinline__ uint32_t smem_to_u32(const void* p) {
    uint32_t a;
    asm("{ .reg .u64 t; cvta.to.shared.u64 t, %1; cvt.u32.u64 %0, t; }" : "=r"(a) : "l"(p));
    return a;
}
__device__ __forceinline__ void ldsm4(uint32_t* r, uint32_t addr) {
    asm volatile("ldmatrix.sync.aligned.m8n8.x4.shared.b16 {%0,%1,%2,%3}, [%4];"
        : "=r"(r[0]), "=r"(r[1]), "=r"(r[2]), "=r"(r[3]) : "r"(addr));
}
__device__ __forceinline__ void ldsm2(uint32_t* r, uint32_t addr) {
    asm volatile("ldmatrix.sync.aligned.m8n8.x2.shared.b16 {%0,%1}, [%2];"
        : "=r"(r[0]), "=r"(r[1]) : "r"(addr));
}
__device__ __forceinline__ void mma16816(float* c, const uint32_t* a, uint32_t b0, uint32_t b1) {
    asm volatile("mma.sync.aligned.m16n8k16.row.col.f32.bf16.bf16.f32 "
        "{%0,%1,%2,%3}, {%4,%5,%6,%7}, {%8,%9}, {%0,%1,%2,%3};"
        : "+f"(c[0]), "+f"(c[1]), "+f"(c[2]), "+f"(c[3])
        : "r"(a[0]), "r"(a[1]), "r"(a[2]), "r"(a[3]), "r"(b0), "r"(b1));
}
__device__ __forceinline__ unsigned long long pack2(float x, float y) {
    unsigned long long r;
    asm("mov.b64 %0, {%1, %2};" : "=l"(r) : "f"(x), "f"(y));
    return r;
}
__device__ __forceinline__ void unpack2(unsigned long long v, float& x, float& y) {
    asm("mov.b64 {%0, %1}, %2;" : "=f"(x), "=f"(y) : "l"(v));
}
__device__ __forceinline__ void ffma2(unsigned long long& c, unsigned long long a, unsigned long long b) {
    asm("fma.rn.f32x2 %0, %1, %2, %0;" : "+l"(c) : "l"(a), "l"(b));
}
__device__ __forceinline__ unsigned long long lds_u64(uint32_t a) {
    unsigned long long v;
    asm volatile("ld.shared.b64 %0, [%1];" : "=l"(v) : "r"(a));
    return v;
}

// ============================================================================
// prep_w: fp32 weights -> bf16 hi/lo.  Only the 6 segs still used as raw
// weights: wv of all mods + thigh wq,wk.
// ============================================================================
__global__ void prep_w(Params p) {
    const int seg_tab[6] = {2, 3, 4, 5, 8, 11};
    const int seg = seg_tab[blockIdx.y];
    const int mod = seg / 3;
    const int Cin = (mod == 1) ? 1280 : 640;
    const float* __restrict__ w = p.w[mod * 6 + (seg % 3)];
    const size_t off = c_offs[seg];
    const size_t n = (size_t)640 * Cin;
    for (size_t i = (size_t)blockIdx.x * blockDim.x + threadIdx.x; i < n; i += (size_t)gridDim.x * blockDim.x) {
        float v = w[i];
        __nv_bfloat16 h = __float2bfloat16(v);
        g_w_hi[off + i] = h;
        g_w_lo[off + i] = __float2bfloat16(v - __bfloat162float(h));
    }
}

// ============================================================================
// prep_mm: M = Wq^T Wk (fp32) -> bf16 hi/lo into the wq slot, for mods 0,2,3.
// M[c1][c2] = sum_o Wq[o][c1]*Wk[o][c2].  CTA = 64x64 tile; grid (100, 3).
// ============================================================================
__global__ __launch_bounds__(256) void prep_mm(Params p) {
    const int mod_tab[3] = {0, 2, 3};
    const int mod = mod_tab[blockIdx.y];
    const float* __restrict__ Wq = p.w[mod * 6 + 0];
    const float* __restrict__ Wk = p.w[mod * 6 + 1];
    const size_t moff = c_offs[mod * 3];

    const int tile = blockIdx.x;
    const int i0 = (tile / 10) * 64, j0 = (tile % 10) * 64;
    const int tid = threadIdx.x;

    __shared__ __align__(16) float Aq[32][68];
    __shared__ __align__(16) float Ak[32][68];

    const int ti = (tid / 16) * 4, tj = (tid % 16) * 4;
    float acc[4][4] = {};

    for (int o0 = 0; o0 < 640; o0 += 32) {
        for (int idx = tid; idx < 512; idx += 256) {
            int r = idx / 16, c4 = (idx % 16) * 4;
            *(float4*)&Aq[r][c4] = *(const float4*)(Wq + (size_t)(o0 + r) * 640 + i0 + c4);
            *(float4*)&Ak[r][c4] = *(const float4*)(Wk + (size_t)(o0 + r) * 640 + j0 + c4);
        }
        __syncthreads();
        #pragma unroll 8
        for (int o = 0; o < 32; o++) {
            float a[4], bv[4];
            #pragma unroll
            for (int ii = 0; ii < 4; ii++) a[ii] = Aq[o][ti + ii];
            #pragma unroll
            for (int jj = 0; jj < 4; jj++) bv[jj] = Ak[o][tj + jj];
            #pragma unroll
            for (int ii = 0; ii < 4; ii++)
                #pragma unroll
                for (int jj = 0; jj < 4; jj++) acc[ii][jj] += a[ii] * bv[jj];
        }
        __syncthreads();
    }

    #pragma unroll
    for (int ii = 0; ii < 4; ii++)
        #pragma unroll
        for (int jj = 0; jj < 4; jj++) {
            float v = acc[ii][jj];
            __nv_bfloat16 h = __float2bfloat16(v);
            size_t o = moff + (size_t)(i0 + ti + ii) * 640 + j0 + tj + jj;
            g_w_hi[o] = h;
            g_w_lo[o] = __float2bfloat16(v - __bfloat162float(h));
        }
}

// ============================================================================
// prep_x: x[b][C=3200][L=100] fp32 -> XT[b][l][c] bf16 hi/lo
// ============================================================================
__global__ void prep_x(const float* __restrict__ x) {
    __shared__ float t[32][33];
    const int b = blockIdx.z, ct = blockIdx.x, lt = blockIdx.y;
    const int tx = threadIdx.x, ty = threadIdx.y;
    const float* xb = x + (size_t)b * 320000;
    const int l = lt * 32 + tx;
    #pragma unroll
    for (int j = 0; j < 4; j++) {
        int c = ct * 32 + ty + j * 8;
        t[ty + j * 8][tx] = (l < 100) ? xb[(size_t)c * 100 + l] : 0.0f;
    }
    __syncthreads();
    const int c_out = ct * 32 + tx;
    const size_t xtb = (size_t)b * 320000;
    #pragma unroll
    for (int j = 0; j < 4; j++) {
        int lo_ = lt * 32 + ty + j * 8;
        if (lo_ < 100) {
            float v = t[tx][ty + j * 8];
            __nv_bfloat16 h = __float2bfloat16(v);
            size_t o = xtb + (size_t)lo_ * 3200 + c_out;
            g_xt_hi[o] = h;
            g_xt_lo[o] = __float2bfloat16(v - __bfloat162float(h));
        }
    }
}

// ============================================================================
// qkv_mma: R9 body (best).  9 projection entries per batch instead of 12:
//   e: 0=(m0,T) 1=(m0,V) 2=(m1,Q) 3=(m1,K) 4=(m1,V) 5=(m2,T) 6=(m2,V)
//      7=(m3,T) 8=(m3,V)
// ============================================================================
#define STAGE  37120u
#define OFF_AH 0u
#define OFF_AL 10240u
#define OFF_BH 20480u
#define OFF_BL 28800u

__constant__ int c_emod[9]  = {0, 0, 1, 1, 1, 2, 2, 3, 3};
__constant__ int c_ewoff[9] = {0, 2, 3, 4, 5, 6, 8, 9, 11};
__constant__ int c_eslot[9] = {0, 2, 0, 1, 2, 0, 2, 0, 2};
__constant__ int c_ebias[9] = {3, 5, 9, 10, 11, 15, 17, 21, 23};

__global__ __launch_bounds__(256, 2) void qkv_mma(Params p) {
    extern __shared__ __align__(16) char smem_raw[];
    const uint32_t sb = smem_to_u32(smem_raw);

    const int tid = threadIdx.x;
    int bid = blockIdx.x;
    const int mtile = bid % 5; bid /= 5;
    const int e     = bid % 9; bid /= 9;
    const int b     = bid;
    const int mod   = c_emod[e];

    const int Cin = (mod == 1) ? 1280 : 640;
    const int nch = Cin >> 5;
    const int mbase = mtile * 128;

    const int c0m_tab[4] = {2560, 640, 1920, 0};
    const size_t woff = c_offs[c_ewoff[e]];
    const size_t xoff = (size_t)b * 320000 + c0m_tab[mod];
    const float* __restrict__ bias = p.w[c_ebias[e]];
    float* __restrict__ O = g_scr + ((((size_t)b * 4 + mod) * 3 + c_eslot[e]) * 640 + mbase) * 100;

    const __nv_bfloat16* __restrict__ Wh = g_w_hi + woff;
    const __nv_bfloat16* __restrict__ Wl = g_w_lo + woff;
    const __nv_bfloat16* __restrict__ Xh = g_xt_hi + xoff;
    const __nv_bfloat16* __restrict__ Xl = g_xt_lo + xoff;

    for (int idx = tid; idx < 320; idx += 256) {
        int st = idx / 160, rest = idx % 160;
        int buf = rest / 80, r2 = rest % 80;
        uint32_t a = sb + (uint32_t)st * STAGE + (buf ? OFF_BL : OFF_BH)
                   + (uint32_t)(100 + r2 / 20) * 80 + (uint32_t)(r2 % 20) * 4;
        asm volatile("st.shared.b32 [%0], %1;" :: "r"(a), "r"(0) : "memory");
    }

    auto issue_chunk = [&](int st, int c) {
        const int k0 = c << 5;
        const uint32_t stg = sb + (uint32_t)st * STAGE;
        for (int idx = tid; idx < 1824; idx += 256) {
            const __nv_bfloat16* src;
            uint32_t dst;
            if (idx < 1024) {
                int buf = idx >> 9, r = (idx >> 2) & 127, seg = idx & 3;
                src = (buf ? Wl : Wh) + (size_t)(mbase + r) * Cin + k0 + seg * 8;
                dst = stg + (buf ? OFF_AL : OFF_AH) + (uint32_t)r * 80 + (uint32_t)seg * 16;
            } else {
                int j = idx - 1024;
                int n = j >> 3, rem = j & 7;
                int buf = rem >> 2, seg = rem & 3;
                src = (buf ? Xl : Xh) + (size_t)n * 3200 + k0 + seg * 8;
                dst = stg + (buf ? OFF_BL : OFF_BH) + (uint32_t)n * 80 + (uint32_t)seg * 16;
            }
            asm volatile("cp.async.cg.shared.global [%0], [%1], 16;" :: "r"(dst), "l"(src) : "memory");
        }
        asm volatile("cp.async.commit_group;" ::: "memory");
    };

    const int w = tid >> 5, lane = tid & 31;
    const int rloc = w * 16 + (lane >> 2);
    const int qd = lane & 3;

    const uint32_t aoff = (uint32_t)(w * 16 + (lane & 15)) * 80 + (uint32_t)(lane >> 4) * 16;
    const uint32_t b4off = (uint32_t)(((lane >> 4) * 8) + (lane & 7)) * 80 + (uint32_t)((lane >> 3) & 1) * 16;
    const uint32_t b2off = (uint32_t)(lane & 7) * 80 + (uint32_t)((lane >> 3) & 1) * 16;

    float acc[13][4];
    #pragma unroll
    for (int t = 0; t < 13; t++)
        #pragma unroll
        for (int i = 0; i < 4; i++) acc[t][i] = 0.0f;

    issue_chunk(0, 0);

    for (int c = 0; c < nch; c++) {
        const int s = c & 1;
        if (c + 1 < nch) {
            issue_chunk(s ^ 1, c + 1);
            asm volatile("cp.async.wait_group 1;" ::: "memory");
        } else {
            asm volatile("cp.async.wait_group 0;" ::: "memory");
        }
        __syncthreads();

        const uint32_t stg = sb + (uint32_t)s * STAGE;
        const uint32_t aAh = stg + OFF_AH + aoff;
        const uint32_t aAl = stg + OFF_AL + aoff;
        const uint32_t aBh4 = stg + OFF_BH + b4off;
        const uint32_t aBl4 = stg + OFF_BL + b4off;
        const uint32_t aBh2 = stg + OFF_BH + 7680u + b2off;
        const uint32_t aBl2 = stg + OFF_BL + 7680u + b2off;

        #pragma unroll
        for (int s16 = 0; s16 < 2; s16++) {
            const uint32_t ko = (uint32_t)s16 * 32;
            uint32_t ah[4], al[4];
            ldsm4(ah, aAh + ko);
            ldsm4(al, aAl + ko);
            #pragma unroll
            for (int pr = 0; pr < 6; pr++) {
                uint32_t bh[4], bl[4];
                ldsm4(bh, aBh4 + (uint32_t)pr * 1280 + ko);
                ldsm4(bl, aBl4 + (uint32_t)pr * 1280 + ko);
                mma16816(acc[2 * pr],     ah, bh[0], bh[1]);
                mma16816(acc[2 * pr + 1], ah, bh[2], bh[3]);
                mma16816(acc[2 * pr],     ah, bl[0], bl[1]);
                mma16816(acc[2 * pr + 1], ah, bl[2], bl[3]);
                mma16816(acc[2 * pr],     al, bh[0], bh[1]);
                mma16816(acc[2 * pr + 1], al, bh[2], bh[3]);
            }
            {
                uint32_t bh[2], bl[2];
                ldsm2(bh, aBh2 + ko);
                ldsm2(bl, aBl2 + ko);
                mma16816(acc[12], ah, bh[0], bh[1]);
                mma16816(acc[12], ah, bl[0], bl[1]);
                mma16816(acc[12], al, bh[0], bh[1]);
            }
        }
        __syncthreads();
    }

    const float bv0 = bias[mbase + rloc];
    const float bv1 = bias[mbase + rloc + 8];
    float* o0 = O + (size_t)rloc * 100;
    float* o1 = o0 + 800;
    #pragma unroll
    for (int t = 0; t < 13; t++) {
        int col = t * 8 + qd * 2;
        if (col < 100) {
            float2 v0 = make_float2(acc[t][0] + bv0, acc[t][1] + bv0);
            float2 v1 = make_float2(acc[t][2] + bv1, acc[t][3] + bv1);
            *(float2*)(o0 + col) = v0;
            *(float2*)(o1 + col) = v1;
        }
    }
}

// ============================================================================
// Pass 2: attention v4 (R9 body).  For small mods the "Q" operand is the raw
// x slice (S = x^T T); for thigh it is scratch Q as before.
// ============================================================================
#define PT_OFF   0
#define U_OFF    10000
#define KC_OFF   3328
#define PART_OFF 16656
#define ROW_OFF  17656
#define ATTN_SMEM 71040

__global__ __launch_bounds__(256, 3) void attn_kernel(const float* __restrict__ x,
                                                      float* __restrict__ out) {
    extern __shared__ __align__(16) float sm[];
    const int tid = threadIdx.x;
    const int bm = blockIdx.x;
    const int mod = bm & 3, b = bm >> 2;

    const float* __restrict__ S0 = g_scr + (size_t)bm * 192000;
    const int c0m_tab[4] = {2560, 640, 1920, 0};
    const float* __restrict__ Qp = (mod == 1)
        ? S0
        : (x + (size_t)b * 320000 + (size_t)c0m_tab[mod] * 100);
    const float* __restrict__ Kp = (mod == 1) ? (S0 + 64000) : S0;
    const float* __restrict__ V = S0 + 128000;
    float* __restrict__ O = out + ((size_t)mod * NB + b) * 64000;

    float* Pt   = sm + PT_OFF;
    float* U    = sm + U_OFF;
    float* part = sm + PART_OFF;
    float* row  = sm + ROW_OFF;
    const uint32_t u_b = smem_to_u32(U);
    const uint32_t pt_b = smem_to_u32(Pt);

    const bool act = tid < 250;
    const int lg = tid % 25;
    const int mg = tid / 25;
    const int m0 = mg * 10;

    unsigned long long acc[4][5];
    #pragma unroll
    for (int t = 0; t < 4; t++)
        #pragma unroll
        for (int j = 0; j < 5; j++) acc[t][j] = 0ULL;

    for (int c0 = 0; c0 < 640; c0 += 32) {
        for (int idx = tid; idx < 1600; idx += 256) {
            int which = idx >= 800;
            int i2 = idx - which * 800;
            int rw = i2 / 25, c4 = (i2 % 25) * 4;
            const float* src = (which ? Kp : Qp) + (size_t)(c0 + rw) * 100 + c4;
            *(float4*)(U + which * KC_OFF + rw * 104 + c4) = *(const float4*)src;
        }
        __syncthreads();
        if (act) {
            #pragma unroll 2
            for (int kk = 0; kk < 32; kk++) {
                const float* qrow = U + kk * 104;
                unsigned long long qd_[4];
                #pragma unroll
                for (int t = 0; t < 4; t++) {
                    float qv = qrow[lg + 25 * t];
                    qd_[t] = pack2(qv, qv);
                }
                const uint32_t kb = u_b + (uint32_t)(KC_OFF + kk * 104 + m0) * 4;
                #pragma unroll
                for (int j = 0; j < 5; j++) {
                    unsigned long long kv = lds_u64(kb + (uint32_t)j * 8);
                    ffma2(acc[0][j], qd_[0], kv);
                    ffma2(acc[1][j], qd_[1], kv);
                    ffma2(acc[2][j], qd_[2], kv);
                    ffma2(acc[3][j], qd_[3], kv);
                }
            }
        }
        __syncthreads();
    }

    if (act) {
        #pragma unroll
        for (int t = 0; t < 4; t++) {
            float mx = -3.4e38f;
            #pragma unroll
            for (int j = 0; j < 5; j++) {
                float lo, hi;
                unpack2(acc[t][j], lo, hi);
                mx = fmaxf(mx, fmaxf(lo, hi));
            }
            part[(lg + 25 * t) * 10 + mg] = mx;
        }
    }
    __syncthreads();
    if (tid < 100) {
        float m = -3.4e38f;
        #pragma unroll
        for (int g = 0; g < 10; g++) m = fmaxf(m, part[tid * 10 + g]);
        row[tid] = m;
    }
    __syncthreads();
    if (act) {
        #pragma unroll
        for (int t = 0; t < 4; t++) {
            float mr = row[lg + 25 * t];
            float s = 0.0f;
            #pragma unroll
            for (int j = 0; j < 5; j++) {
                float lo, hi;
                unpack2(acc[t][j], lo, hi);
                float e0 = __expf(lo - mr), e1 = __expf(hi - mr);
                s += e0 + e1;
                acc[t][j] = pack2(e0, e1);
            }
            part[(lg + 25 * t) * 10 + mg] = s;
        }
    }
    __syncthreads();
    if (tid < 100) {
        float s = 0.0f;
        #pragma unroll
        for (int g = 0; g < 10; g++) s += part[tid * 10 + g];
        row[tid] = 1.0f / s;
    }
    __syncthreads();
    if (act) {
        #pragma unroll
        for (int t = 0; t < 4; t++) {
            int l = lg + 25 * t;
            float inv = row[l];
            #pragma unroll
            for (int j = 0; j < 5; j++) {
                float lo, hi;
                unpack2(acc[t][j], lo, hi);
                int m = m0 + 2 * j;
                Pt[m * 100 + l]       = lo * inv;
                Pt[(m + 1) * 100 + l] = hi * inv;
            }
        }
    }

    const int cgC = tid % 16, igC = tid / 16;
    const bool actC = igC < 10;
    const int i0 = igC * 10;

    for (int chunk = 0; chunk < 10; chunk++) {
        __syncthreads();
        for (int idx = tid; idx < 1600; idx += 256) {
            int rw = idx / 25, c4 = (idx % 25) * 4;
            *(float4*)(U + rw * 100 + c4) =
                *(const float4*)(V + (size_t)(chunk * 64 + rw) * 100 + c4);
        }
        __syncthreads();
        if (actC) {
            unsigned long long pacc[4][5];
            #pragma unroll
            for (int u = 0; u < 4; u++)
                #pragma unroll
                for (int s = 0; s < 5; s++) pacc[u][s] = 0ULL;
            const uint32_t pb = pt_b + (uint32_t)i0 * 4;
            #pragma unroll 4
            for (int j = 0; j < 100; j++) {
                unsigned long long vd[4];
                #pragma unroll
                for (int u = 0; u < 4; u++) {
                    float vv = U[(cgC + 16 * u) * 100 + j];
                    vd[u] = pack2(vv, vv);
                }
                const uint32_t pj = pb + (uint32_t)j * 400;
                #pragma unroll
                for (int s = 0; s < 5; s++) {
                    unsigned long long pp = lds_u64(pj + (uint32_t)s * 8);
                    ffma2(pacc[0][s], vd[0], pp);
                    ffma2(pacc[1][s], vd[1], pp);
                    ffma2(pacc[2][s], vd[2], pp);
                    ffma2(pacc[3][s], vd[3], pp);
                }
            }
            #pragma unroll
            for (int u = 0; u < 4; u++) {
                int c_ = chunk * 64 + cgC + 16 * u;
                float* orow = O + (size_t)c_ * 100 + i0;
                #pragma unroll
                for (int s = 0; s < 5; s++) {
                    float a0, a1;
                    unpack2(pacc[u][s], a0, a1);
                    *(float2*)(orow + 2 * s) = make_float2(a0, a1);
                }
            }
        }
    }
}

extern "C" void kernel_launch(void* const* d_in, const int* in_sizes, int n_in,
                              void* d_out, int out_size) {
    const float* x = (const float*)d_in[0];
    Params p;
    for (int i = 0; i < 24; i++) p.w[i] = (const float*)d_in[1 + i];

    prep_w<<<dim3(800, 6), 256>>>(p);
    prep_mm<<<dim3(100, 3), 256>>>(p);
    prep_x<<<dim3(100, 4, 256), dim3(32, 8)>>>(x);

    cudaFuncSetAttribute(qkv_mma, cudaFuncAttributeMaxDynamicSharedMemorySize, 74240);
    qkv_mma<<<11520, 256, 74240>>>(p);

    cudaFuncSetAttribute(attn_kernel, cudaFuncAttributeMaxDynamicSharedMemorySize, ATTN_SMEM);
    attn_kernel<<<1024, 256, ATTN_SMEM>>>(x, (float*)d_out);
}

// round 14
// speedup vs baseline: 1.2414x; 1.0199x over previous
#include <cuda_runtime.h>
#include <cuda_bf16.h>
#include <cstdint>

#define NB 256

// Scratch: [b][mod][slot(0,1,2)][640][100] fp32
// small mods: slot0 = T (= WqT*Wk*x), slot2 = V.  thigh: slot0=Q, slot1=K, slot2=V.
__device__ float g_scr[196608000UL];
__device__ __nv_bfloat16 g_w_hi[6144000];
__device__ __nv_bfloat16 g_w_lo[6144000];
__device__ __nv_bfloat16 g_xt_hi[81920000UL];   // [b][l=100][c=3200]
__device__ __nv_bfloat16 g_xt_lo[81920000UL];

struct Params {
    const float* w[24];  // [mod][wq,wk,wv,bq,bk,bv]
};

__constant__ size_t c_offs[12] = {0, 409600, 819200, 1228800, 2048000, 2867200,
                                  3686400, 4096000, 4505600, 4915200, 5324800, 5734400};

// ---------------------------------------------------------------- helpers
__device__ __forceinline__ uint32_t smem_to_u32(const void* p) {
    uint32_t a;
    asm("{ .reg .u64 t; cvta.to.shared.u64 t, %1; cvt.u32.u64 %0, t; }" : "=r"(a) : "l"(p));
    return a;
}
__device__ __forceinline__ void ldsm4(uint32_t* r, uint32_t addr) {
    asm volatile("ldmatrix.sync.aligned.m8n8.x4.shared.b16 {%0,%1,%2,%3}, [%4];"
        : "=r"(r[0]), "=r"(r[1]), "=r"(r[2]), "=r"(r[3]) : "r"(addr));
}
__device__ __forceinline__ void ldsm2(uint32_t* r, uint32_t addr) {
    asm volatile("ldmatrix.sync.aligned.m8n8.x2.shared.b16 {%0,%1}, [%2];"
        : "=r"(r[0]), "=r"(r[1]) : "r"(addr));
}
__device__ __forceinline__ void mma16816(float* c, const uint32_t* a, uint32_t b0, uint32_t b1) {
    asm volatile("mma.sync.aligned.m16n8k16.row.col.f32.bf16.bf16.f32 "
        "{%0,%1,%2,%3}, {%4,%5,%6,%7}, {%8,%9}, {%0,%1,%2,%3};"
        : "+f"(c[0]), "+f"(c[1]), "+f"(c[2]), "+f"(c[3])
        : "r"(a[0]), "r"(a[1]), "r"(a[2]), "r"(a[3]), "r"(b0), "r"(b1));
}
__device__ __forceinline__ unsigned long long pack2(float x, float y) {
    unsigned long long r;
    asm("mov.b64 %0, {%1, %2};" : "=l"(r) : "f"(x), "f"(y));
    return r;
}
__device__ __forceinline__ void unpack2(unsigned long long v, float& x, float& y) {
    asm("mov.b64 {%0, %1}, %2;" : "=f"(x), "=f"(y) : "l"(v));
}
__device__ __forceinline__ void ffma2(unsigned long long& c, unsigned long long a, unsigned long long b) {
    asm("fma.rn.f32x2 %0, %1, %2, %0;" : "+l"(c) : "l"(a), "l"(b));
}
__device__ __forceinline__ unsigned long long lds_u64(uint32_t a) {
    unsigned long long v;
    asm volatile("ld.shared.b64 %0, [%1];" : "=l"(v) : "r"(a));
    return v;
}

// ============================================================================
// prep_w: fp32 weights -> bf16 hi/lo.  Only the 6 segs still used as raw
// weights: wv of all mods + thigh wq,wk.
// ============================================================================
__global__ void prep_w(Params p) {
    const int seg_tab[6] = {2, 3, 4, 5, 8, 11};
    const int seg = seg_tab[blockIdx.y];
    const int mod = seg / 3;
    const int Cin = (mod == 1) ? 1280 : 640;
    const float* __restrict__ w = p.w[mod * 6 + (seg % 3)];
    const size_t off = c_offs[seg];
    const size_t n = (size_t)640 * Cin;
    for (size_t i = (size_t)blockIdx.x * blockDim.x + threadIdx.x; i < n; i += (size_t)gridDim.x * blockDim.x) {
        float v = w[i];
        __nv_bfloat16 h = __float2bfloat16(v);
        g_w_hi[off + i] = h;
        g_w_lo[off + i] = __float2bfloat16(v - __bfloat162float(h));
    }
}

// ============================================================================
// prep_mm: M = Wq^T Wk (fp32) -> bf16 hi/lo into the wq slot, for mods 0,2,3.
// ============================================================================
__global__ __launch_bounds__(256) void prep_mm(Params p) {
    const int mod_tab[3] = {0, 2, 3};
    const int mod = mod_tab[blockIdx.y];
    const float* __restrict__ Wq = p.w[mod * 6 + 0];
    const float* __restrict__ Wk = p.w[mod * 6 + 1];
    const size_t moff = c_offs[mod * 3];

    const int tile = blockIdx.x;
    const int i0 = (tile / 10) * 64, j0 = (tile % 10) * 64;
    const int tid = threadIdx.x;

    __shared__ __align__(16) float Aq[32][68];
    __shared__ __align__(16) float Ak[32][68];

    const int ti = (tid / 16) * 4, tj = (tid % 16) * 4;
    float acc[4][4] = {};

    for (int o0 = 0; o0 < 640; o0 += 32) {
        for (int idx = tid; idx < 512; idx += 256) {
            int r = idx / 16, c4 = (idx % 16) * 4;
            *(float4*)&Aq[r][c4] = *(const float4*)(Wq + (size_t)(o0 + r) * 640 + i0 + c4);
            *(float4*)&Ak[r][c4] = *(const float4*)(Wk + (size_t)(o0 + r) * 640 + j0 + c4);
        }
        __syncthreads();
        #pragma unroll 8
        for (int o = 0; o < 32; o++) {
            float a[4], bv[4];
            #pragma unroll
            for (int ii = 0; ii < 4; ii++) a[ii] = Aq[o][ti + ii];
            #pragma unroll
            for (int jj = 0; jj < 4; jj++) bv[jj] = Ak[o][tj + jj];
            #pragma unroll
            for (int ii = 0; ii < 4; ii++)
                #pragma unroll
                for (int jj = 0; jj < 4; jj++) acc[ii][jj] += a[ii] * bv[jj];
        }
        __syncthreads();
    }

    #pragma unroll
    for (int ii = 0; ii < 4; ii++)
        #pragma unroll
        for (int jj = 0; jj < 4; jj++) {
            float v = acc[ii][jj];
            __nv_bfloat16 h = __float2bfloat16(v);
            size_t o = moff + (size_t)(i0 + ti + ii) * 640 + j0 + tj + jj;
            g_w_hi[o] = h;
            g_w_lo[o] = __float2bfloat16(v - __bfloat162float(h));
        }
}

// ============================================================================
// prep_x: x[b][C=3200][L=100] fp32 -> XT[b][l][c] bf16 hi/lo
// ============================================================================
__global__ void prep_x(const float* __restrict__ x) {
    __shared__ float t[32][33];
    const int b = blockIdx.z, ct = blockIdx.x, lt = blockIdx.y;
    const int tx = threadIdx.x, ty = threadIdx.y;
    const float* xb = x + (size_t)b * 320000;
    const int l = lt * 32 + tx;
    #pragma unroll
    for (int j = 0; j < 4; j++) {
        int c = ct * 32 + ty + j * 8;
        t[ty + j * 8][tx] = (l < 100) ? xb[(size_t)c * 100 + l] : 0.0f;
    }
    __syncthreads();
    const int c_out = ct * 32 + tx;
    const size_t xtb = (size_t)b * 320000;
    #pragma unroll
    for (int j = 0; j < 4; j++) {
        int lo_ = lt * 32 + ty + j * 8;
        if (lo_ < 100) {
            float v = t[tx][ty + j * 8];
            __nv_bfloat16 h = __float2bfloat16(v);
            size_t o = xtb + (size_t)lo_ * 3200 + c_out;
            g_xt_hi[o] = h;
            g_xt_lo[o] = __float2bfloat16(v - __bfloat162float(h));
        }
    }
}

// ============================================================================
// qkv_mma: R13 body; __launch_bounds__(256,3) to cap regs at 85 and fit
// 3 CTAs/SM (3 x 74240 B = 222720 <= 228KB carveout).
// ============================================================================
#define STAGE  37120u
#define OFF_AH 0u
#define OFF_AL 10240u
#define OFF_BH 20480u
#define OFF_BL 28800u

__constant__ int c_emod[9]  = {0, 0, 1, 1, 1, 2, 2, 3, 3};
__constant__ int c_ewoff[9] = {0, 2, 3, 4, 5, 6, 8, 9, 11};
__constant__ int c_eslot[9] = {0, 2, 0, 1, 2, 0, 2, 0, 2};
__constant__ int c_ebias[9] = {3, 5, 9, 10, 11, 15, 17, 21, 23};

__global__ __launch_bounds__(256, 3) void qkv_mma(Params p) {
    extern __shared__ __align__(16) char smem_raw[];
    const uint32_t sb = smem_to_u32(smem_raw);

    const int tid = threadIdx.x;
    int bid = blockIdx.x;
    const int mtile = bid % 5; bid /= 5;
    const int e     = bid % 9; bid /= 9;
    const int b     = bid;
    const int mod   = c_emod[e];

    const int Cin = (mod == 1) ? 1280 : 640;
    const int nch = Cin >> 5;
    const int mbase = mtile * 128;

    const int c0m_tab[4] = {2560, 640, 1920, 0};
    const size_t woff = c_offs[c_ewoff[e]];
    const size_t xoff = (size_t)b * 320000 + c0m_tab[mod];
    const float* __restrict__ bias = p.w[c_ebias[e]];
    float* __restrict__ O = g_scr + ((((size_t)b * 4 + mod) * 3 + c_eslot[e]) * 640 + mbase) * 100;

    const __nv_bfloat16* __restrict__ Wh = g_w_hi + woff;
    const __nv_bfloat16* __restrict__ Wl = g_w_lo + woff;
    const __nv_bfloat16* __restrict__ Xh = g_xt_hi + xoff;
    const __nv_bfloat16* __restrict__ Xl = g_xt_lo + xoff;

    for (int idx = tid; idx < 320; idx += 256) {
        int st = idx / 160, rest = idx % 160;
        int buf = rest / 80, r2 = rest % 80;
        uint32_t a = sb + (uint32_t)st * STAGE + (buf ? OFF_BL : OFF_BH)
                   + (uint32_t)(100 + r2 / 20) * 80 + (uint32_t)(r2 % 20) * 4;
        asm volatile("st.shared.b32 [%0], %1;" :: "r"(a), "r"(0) : "memory");
    }

    auto issue_chunk = [&](int st, int c) {
        const int k0 = c << 5;
        const uint32_t stg = sb + (uint32_t)st * STAGE;
        for (int idx = tid; idx < 1824; idx += 256) {
            const __nv_bfloat16* src;
            uint32_t dst;
            if (idx < 1024) {
                int buf = idx >> 9, r = (idx >> 2) & 127, seg = idx & 3;
                src = (buf ? Wl : Wh) + (size_t)(mbase + r) * Cin + k0 + seg * 8;
                dst = stg + (buf ? OFF_AL : OFF_AH) + (uint32_t)r * 80 + (uint32_t)seg * 16;
            } else {
                int j = idx - 1024;
                int n = j >> 3, rem = j & 7;
                int buf = rem >> 2, seg = rem & 3;
                src = (buf ? Xl : Xh) + (size_t)n * 3200 + k0 + seg * 8;
                dst = stg + (buf ? OFF_BL : OFF_BH) + (uint32_t)n * 80 + (uint32_t)seg * 16;
            }
            asm volatile("cp.async.cg.shared.global [%0], [%1], 16;" :: "r"(dst), "l"(src) : "memory");
        }
        asm volatile("cp.async.commit_group;" ::: "memory");
    };

    const int w = tid >> 5, lane = tid & 31;
    const int rloc = w * 16 + (lane >> 2);
    const int qd = lane & 3;

    const uint32_t aoff = (uint32_t)(w * 16 + (lane & 15)) * 80 + (uint32_t)(lane >> 4) * 16;
    const uint32_t b4off = (uint32_t)(((lane >> 4) * 8) + (lane & 7)) * 80 + (uint32_t)((lane >> 3) & 1) * 16;
    const uint32_t b2off = (uint32_t)(lane & 7) * 80 + (uint32_t)((lane >> 3) & 1) * 16;

    float acc[13][4];
    #pragma unroll
    for (int t = 0; t < 13; t++)
        #pragma unroll
        for (int i = 0; i < 4; i++) acc[t][i] = 0.0f;

    issue_chunk(0, 0);

    for (int c = 0; c < nch; c++) {
        const int s = c & 1;
        if (c + 1 < nch) {
            issue_chunk(s ^ 1, c + 1);
            asm volatile("cp.async.wait_group 1;" ::: "memory");
        } else {
            asm volatile("cp.async.wait_group 0;" ::: "memory");
        }
        __syncthreads();

        const uint32_t stg = sb + (uint32_t)s * STAGE;
        const uint32_t aAh = stg + OFF_AH + aoff;
        const uint32_t aAl = stg + OFF_AL + aoff;
        const uint32_t aBh4 = stg + OFF_BH + b4off;
        const uint32_t aBl4 = stg + OFF_BL + b4off;
        const uint32_t aBh2 = stg + OFF_BH + 7680u + b2off;
        const uint32_t aBl2 = stg + OFF_BL + 7680u + b2off;

        #pragma unroll
        for (int s16 = 0; s16 < 2; s16++) {
            const uint32_t ko = (uint32_t)s16 * 32;
            uint32_t ah[4], al[4];
            ldsm4(ah, aAh + ko);
            ldsm4(al, aAl + ko);
            #pragma unroll
            for (int pr = 0; pr < 6; pr++) {
                uint32_t bh[4], bl[4];
                ldsm4(bh, aBh4 + (uint32_t)pr * 1280 + ko);
                ldsm4(bl, aBl4 + (uint32_t)pr * 1280 + ko);
                mma16816(acc[2 * pr],     ah, bh[0], bh[1]);
                mma16816(acc[2 * pr + 1], ah, bh[2], bh[3]);
                mma16816(acc[2 * pr],     ah, bl[0], bl[1]);
                mma16816(acc[2 * pr + 1], ah, bl[2], bl[3]);
                mma16816(acc[2 * pr],     al, bh[0], bh[1]);
                mma16816(acc[2 * pr + 1], al, bh[2], bh[3]);
            }
            {
                uint32_t bh[2], bl[2];
                ldsm2(bh, aBh2 + ko);
                ldsm2(bl, aBl2 + ko);
                mma16816(acc[12], ah, bh[0], bh[1]);
                mma16816(acc[12], ah, bl[0], bl[1]);
                mma16816(acc[12], al, bh[0], bh[1]);
            }
        }
        __syncthreads();
    }

    const float bv0 = bias[mbase + rloc];
    const float bv1 = bias[mbase + rloc + 8];
    float* o0 = O + (size_t)rloc * 100;
    float* o1 = o0 + 800;
    #pragma unroll
    for (int t = 0; t < 13; t++) {
        int col = t * 8 + qd * 2;
        if (col < 100) {
            float2 v0 = make_float2(acc[t][0] + bv0, acc[t][1] + bv0);
            float2 v1 = make_float2(acc[t][2] + bv1, acc[t][3] + bv1);
            *(float2*)(o0 + col) = v0;
            *(float2*)(o1 + col) = v1;
        }
    }
}

// ============================================================================
// Pass 2: attention v4 (R9 body).  For small mods the "Q" operand is the raw
// x slice (S = x^T T); for thigh it is scratch Q as before.
// ============================================================================
#define PT_OFF   0
#define U_OFF    10000
#define KC_OFF   3328
#define PART_OFF 16656
#define ROW_OFF  17656
#define ATTN_SMEM 71040

__global__ __launch_bounds__(256, 3) void attn_kernel(const float* __restrict__ x,
                                                      float* __restrict__ out) {
    extern __shared__ __align__(16) float sm[];
    const int tid = threadIdx.x;
    const int bm = blockIdx.x;
    const int mod = bm & 3, b = bm >> 2;

    const float* __restrict__ S0 = g_scr + (size_t)bm * 192000;
    const int c0m_tab[4] = {2560, 640, 1920, 0};
    const float* __restrict__ Qp = (mod == 1)
        ? S0
        : (x + (size_t)b * 320000 + (size_t)c0m_tab[mod] * 100);
    const float* __restrict__ Kp = (mod == 1) ? (S0 + 64000) : S0;
    const float* __restrict__ V = S0 + 128000;
    float* __restrict__ O = out + ((size_t)mod * NB + b) * 64000;

    float* Pt   = sm + PT_OFF;
    float* U    = sm + U_OFF;
    float* part = sm + PART_OFF;
    float* row  = sm + ROW_OFF;
    const uint32_t u_b = smem_to_u32(U);
    const uint32_t pt_b = smem_to_u32(Pt);

    const bool act = tid < 250;
    const int lg = tid % 25;
    const int mg = tid / 25;
    const int m0 = mg * 10;

    unsigned long long acc[4][5];
    #pragma unroll
    for (int t = 0; t < 4; t++)
        #pragma unroll
        for (int j = 0; j < 5; j++) acc[t][j] = 0ULL;

    for (int c0 = 0; c0 < 640; c0 += 32) {
        for (int idx = tid; idx < 1600; idx += 256) {
            int which = idx >= 800;
            int i2 = idx - which * 800;
            int rw = i2 / 25, c4 = (i2 % 25) * 4;
            const float* src = (which ? Kp : Qp) + (size_t)(c0 + rw) * 100 + c4;
            *(float4*)(U + which * KC_OFF + rw * 104 + c4) = *(const float4*)src;
        }
        __syncthreads();
        if (act) {
            #pragma unroll 2
            for (int kk = 0; kk < 32; kk++) {
                const float* qrow = U + kk * 104;
                unsigned long long qd_[4];
                #pragma unroll
                for (int t = 0; t < 4; t++) {
                    float qv = qrow[lg + 25 * t];
                    qd_[t] = pack2(qv, qv);
                }
                const uint32_t kb = u_b + (uint32_t)(KC_OFF + kk * 104 + m0) * 4;
                #pragma unroll
                for (int j = 0; j < 5; j++) {
                    unsigned long long kv = lds_u64(kb + (uint32_t)j * 8);
                    ffma2(acc[0][j], qd_[0], kv);
                    ffma2(acc[1][j], qd_[1], kv);
                    ffma2(acc[2][j], qd_[2], kv);
                    ffma2(acc[3][j], qd_[3], kv);
                }
            }
        }
        __syncthreads();
    }

    if (act) {
        #pragma unroll
        for (int t = 0; t < 4; t++) {
            float mx = -3.4e38f;
            #pragma unroll
            for (int j = 0; j < 5; j++) {
                float lo, hi;
                unpack2(acc[t][j], lo, hi);
                mx = fmaxf(mx, fmaxf(lo, hi));
            }
            part[(lg + 25 * t) * 10 + mg] = mx;
        }
    }
    __syncthreads();
    if (tid < 100) {
        float m = -3.4e38f;
        #pragma unroll
        for (int g = 0; g < 10; g++) m = fmaxf(m, part[tid * 10 + g]);
        row[tid] = m;
    }
    __syncthreads();
    if (act) {
        #pragma unroll
        for (int t = 0; t < 4; t++) {
            float mr = row[lg + 25 * t];
            float s = 0.0f;
            #pragma unroll
            for (int j = 0; j < 5; j++) {
                float lo, hi;
                unpack2(acc[t][j], lo, hi);
                float e0 = __expf(lo - mr), e1 = __expf(hi - mr);
                s += e0 + e1;
                acc[t][j] = pack2(e0, e1);
            }
            part[(lg + 25 * t) * 10 + mg] = s;
        }
    }
    __syncthreads();
    if (tid < 100) {
        float s = 0.0f;
        #pragma unroll
        for (int g = 0; g < 10; g++) s += part[tid * 10 + g];
        row[tid] = 1.0f / s;
    }
    __syncthreads();
    if (act) {
        #pragma unroll
        for (int t = 0; t < 4; t++) {
            int l = lg + 25 * t;
            float inv = row[l];
            #pragma unroll
            for (int j = 0; j < 5; j++) {
                float lo, hi;
                unpack2(acc[t][j], lo, hi);
                int m = m0 + 2 * j;
                Pt[m * 100 + l]       = lo * inv;
                Pt[(m + 1) * 100 + l] = hi * inv;
            }
        }
    }

    const int cgC = tid % 16, igC = tid / 16;
    const bool actC = igC < 10;
    const int i0 = igC * 10;

    for (int chunk = 0; chunk < 10; chunk++) {
        __syncthreads();
        for (int idx = tid; idx < 1600; idx += 256) {
            int rw = idx / 25, c4 = (idx % 25) * 4;
            *(float4*)(U + rw * 100 + c4) =
                *(const float4*)(V + (size_t)(chunk * 64 + rw) * 100 + c4);
        }
        __syncthreads();
        if (actC) {
            unsigned long long pacc[4][5];
            #pragma unroll
            for (int u = 0; u < 4; u++)
                #pragma unroll
                for (int s = 0; s < 5; s++) pacc[u][s] = 0ULL;
            const uint32_t pb = pt_b + (uint32_t)i0 * 4;
            #pragma unroll 4
            for (int j = 0; j < 100; j++) {
                unsigned long long vd[4];
                #pragma unroll
                for (int u = 0; u < 4; u++) {
                    float vv = U[(cgC + 16 * u) * 100 + j];
                    vd[u] = pack2(vv, vv);
                }
                const uint32_t pj = pb + (uint32_t)j * 400;
                #pragma unroll
                for (int s = 0; s < 5; s++) {
                    unsigned long long pp = lds_u64(pj + (uint32_t)s * 8);
                    ffma2(pacc[0][s], vd[0], pp);
                    ffma2(pacc[1][s], vd[1], pp);
                    ffma2(pacc[2][s], vd[2], pp);
                    ffma2(pacc[3][s], vd[3], pp);
                }
            }
            #pragma unroll
            for (int u = 0; u < 4; u++) {
                int c_ = chunk * 64 + cgC + 16 * u;
                float* orow = O + (size_t)c_ * 100 + i0;
                #pragma unroll
                for (int s = 0; s < 5; s++) {
                    float a0, a1;
                    unpack2(pacc[u][s], a0, a1);
                    *(float2*)(orow + 2 * s) = make_float2(a0, a1);
                }
            }
        }
    }
}

extern "C" void kernel_launch(void* const* d_in, const int* in_sizes, int n_in,
                              void* d_out, int out_size) {
    const float* x = (const float*)d_in[0];
    Params p;
    for (int i = 0; i < 24; i++) p.w[i] = (const float*)d_in[1 + i];

    prep_w<<<dim3(800, 6), 256>>>(p);
    prep_mm<<<dim3(100, 3), 256>>>(p);
    prep_x<<<dim3(100, 4, 256), dim3(32, 8)>>>(x);

    cudaFuncSetAttribute(qkv_mma, cudaFuncAttributeMaxDynamicSharedMemorySize, 74240);
    cudaFuncSetAttribute(qkv_mma, cudaFuncAttributePreferredSharedMemoryCarveout, 100);
    qkv_mma<<<11520, 256, 74240>>>(p);

    cudaFuncSetAttribute(attn_kernel, cudaFuncAttributeMaxDynamicSharedMemorySize, ATTN_SMEM);
    attn_kernel<<<1024, 256, ATTN_SMEM>>>(x, (float*)d_out);
}